// round 3
// baseline (speedup 1.0000x reference)
#include <cuda_runtime.h>
#include <cuda_bf16.h>
#include <cstdint>

// ---------------------------------------------------------------------------
// Problem constants
// ---------------------------------------------------------------------------
#define BATCH   32
#define FRAMES  32
#define NOBJ    36
#define DIN     2048
#define PDIM    512
#define MROWS   (BATCH*FRAMES*NOBJ)     // 36864
#define HEADS   (BATCH*FRAMES)          // 1024
#define NCAT    (4*PDIM)                // 2048 concat output cols
#define NCH     (DIN/64)                // 32 K-chunks of 64

// GEMM tiling
#define MTILE   128
#define NTILE   128
#define KC      64                       // bf16 elems per chunk (128 bytes)
#define STAGES  3

// smem stage layout (bytes)
#define OFF_AH  0
#define OFF_AL  16384
#define OFF_BH  32768
#define OFF_BL  49152
#define STAGE_BYTES 65536
#define GEMM_SMEM  (STAGES*STAGE_BYTES)                  // 196608

#define ATTN_SMEM  ((2*NOBJ*PDIM + NOBJ*NOBJ)*4)         // 152640 bytes

#define OUT_HALF   ((size_t)MROWS*PDIM)

// ---------------------------------------------------------------------------
// Device scratch (static __device__ globals; runtime allocation is forbidden)
// ---------------------------------------------------------------------------
__device__ __nv_bfloat16 g_xh[(size_t)MROWS*DIN];
__device__ __nv_bfloat16 g_xl[(size_t)MROWS*DIN];
__device__ __nv_bfloat16 g_wth[(size_t)NCAT*DIN];   // [n][k], K-major
__device__ __nv_bfloat16 g_wtl[(size_t)NCAT*DIN];
__device__ float g_sig[(size_t)MROWS*PDIM];
__device__ float g_psi[(size_t)MROWS*PDIM];
__device__ float g_v  [(size_t)MROWS*PDIM];

// ---------------------------------------------------------------------------
// PTX helpers (baseline-PTX features only: cp.async, ldmatrix, mma.sync)
// ---------------------------------------------------------------------------
__device__ __forceinline__ uint32_t smem_u32(const void* p) {
    uint32_t a;
    asm("{ .reg .u64 t; cvta.to.shared.u64 t, %1; cvt.u32.u64 %0, t; }"
        : "=r"(a) : "l"(p));
    return a;
}

__device__ __forceinline__ void cp16(uint32_t s, const void* g) {
    asm volatile("cp.async.cg.shared.global [%0], [%1], 16;\n" :: "r"(s), "l"(g) : "memory");
}

#define LDSM4(R, A) \
    asm volatile("ldmatrix.sync.aligned.m8n8.x4.shared.b16 {%0,%1,%2,%3}, [%4];" \
        : "=r"((R)[0]), "=r"((R)[1]), "=r"((R)[2]), "=r"((R)[3]) : "r"(A))

#define MMA(C, A, B0, B1) \
    asm volatile("mma.sync.aligned.m16n8k16.row.col.f32.bf16.bf16.f32 " \
        "{%0,%1,%2,%3}, {%4,%5,%6,%7}, {%8,%9}, {%0,%1,%2,%3};" \
        : "+f"((C)[0]), "+f"((C)[1]), "+f"((C)[2]), "+f"((C)[3]) \
        : "r"((A)[0]), "r"((A)[1]), "r"((A)[2]), "r"((A)[3]), "r"(B0), "r"(B1))

// ---------------------------------------------------------------------------
// Prep kernels: fp32 -> (bf16 hi, bf16 lo) splits
// ---------------------------------------------------------------------------
__global__ void split_x_kernel(const float* __restrict__ x, long n4) {
    long i = blockIdx.x * (long)blockDim.x + threadIdx.x;
    long stride = (long)gridDim.x * blockDim.x;
    __nv_bfloat162* xh2 = reinterpret_cast<__nv_bfloat162*>(g_xh);
    __nv_bfloat162* xl2 = reinterpret_cast<__nv_bfloat162*>(g_xl);
    for (; i < n4; i += stride) {
        float4 v = reinterpret_cast<const float4*>(x)[i];
        __nv_bfloat16 h0 = __float2bfloat16(v.x);
        __nv_bfloat16 h1 = __float2bfloat16(v.y);
        __nv_bfloat16 h2 = __float2bfloat16(v.z);
        __nv_bfloat16 h3 = __float2bfloat16(v.w);
        __nv_bfloat16 l0 = __float2bfloat16(v.x - __bfloat162float(h0));
        __nv_bfloat16 l1 = __float2bfloat16(v.y - __bfloat162float(h1));
        __nv_bfloat16 l2 = __float2bfloat16(v.z - __bfloat162float(h2));
        __nv_bfloat16 l3 = __float2bfloat16(v.w - __bfloat162float(h3));
        __nv_bfloat162 hA; hA.x = h0; hA.y = h1;
        __nv_bfloat162 hB; hB.x = h2; hB.y = h3;
        __nv_bfloat162 lA; lA.x = l0; lA.y = l1;
        __nv_bfloat162 lB; lB.x = l2; lB.y = l3;
        xh2[2*i]   = hA; xh2[2*i+1] = hB;
        xl2[2*i]   = lA; xl2[2*i+1] = lB;
    }
}

__global__ void split_w_kernel(const float* __restrict__ Wp, const float* __restrict__ Ws,
                               const float* __restrict__ Wq, const float* __restrict__ Wr) {
    long t = blockIdx.x * (long)blockDim.x + threadIdx.x;   // over NCAT*DIN
    if (t >= (long)NCAT * DIN) return;
    int n = (int)(t >> 11);        // /DIN
    int k = (int)(t & (DIN - 1));
    int mat = n >> 9, p = n & 511;
    const float* W = (mat == 0) ? Wp : (mat == 1) ? Ws : (mat == 2) ? Wq : Wr;
    float w = W[(size_t)k * PDIM + p];
    __nv_bfloat16 h = __float2bfloat16(w);
    g_wth[t] = h;
    g_wtl[t] = __float2bfloat16(w - __bfloat162float(h));
}

// ---------------------------------------------------------------------------
// GEMM: out[m][n] = sum_k x[m][k] * Wcat[k][n], bf16 3-pass, fp32 accumulate
// mma.sync.m16n8k16 (HMMA) — tcgen05 is unavailable at this PTX target.
// ---------------------------------------------------------------------------
__device__ __forceinline__ void load_chunk(uint32_t sbase, int kc, int m0, int n0, int tid) {
    const char* xh = (const char*)g_xh;
    const char* xl = (const char*)g_xl;
    const char* bh = (const char*)g_wth;
    const char* bl = (const char*)g_wtl;
    size_t kcoff = (size_t)kc * 128;   // 64 bf16 = 128 bytes
#pragma unroll
    for (int q = 0; q < 4; q++) {                 // 128 rows x 8 x 16B segments
        int j = tid + q * 256;
        int r = j >> 3, i = j & 7;
        uint32_t so = (uint32_t)(r * 128 + ((i * 16) ^ ((r & 7) << 4)));
        size_t goA = ((size_t)(m0 + r)) * (DIN * 2) + kcoff + i * 16;
        size_t goB = ((size_t)(n0 + r)) * (DIN * 2) + kcoff + i * 16;
        cp16(sbase + OFF_AH + so, xh + goA);
        cp16(sbase + OFF_AL + so, xl + goA);
        cp16(sbase + OFF_BH + so, bh + goB);
        cp16(sbase + OFF_BL + so, bl + goB);
    }
    asm volatile("cp.async.commit_group;\n" ::: "memory");
}

__device__ __forceinline__ void compute_chunk(uint32_t sbase, float (*acc)[8][4],
                                              int wm, int wn, int lane) {
    int r_off  = lane & 15;
    int kseg   = (lane >> 4) << 3;            // A: 0 or 8 (k halves)
    int n_off  = (lane & 7) + ((lane >> 4) << 3);
    int ksegb  = ((lane >> 3) & 1) << 3;      // B: 0 or 8
#pragma unroll
    for (int kk = 0; kk < 4; kk++) {          // 4 x k16 per 64-chunk
        uint32_t ah[2][4], al[2][4], bh[4][4], bl[4][4];
#pragma unroll
        for (int im = 0; im < 2; im++) {
            uint32_t row = wm + im * 16 + r_off;
            uint32_t kb  = (uint32_t)((kk * 16 + kseg) * 2);
            uint32_t off = row * 128 + (kb ^ ((row & 7) << 4));
            LDSM4(ah[im], sbase + OFF_AH + off);
            LDSM4(al[im], sbase + OFF_AL + off);
        }
#pragma unroll
        for (int j = 0; j < 4; j++) {
            uint32_t row = wn + j * 16 + n_off;
            uint32_t kb  = (uint32_t)((kk * 16 + ksegb) * 2);
            uint32_t off = row * 128 + (kb ^ ((row & 7) << 4));
            LDSM4(bh[j], sbase + OFF_BH + off);
            LDSM4(bl[j], sbase + OFF_BL + off);
        }
#pragma unroll
        for (int im = 0; im < 2; im++) {
#pragma unroll
            for (int j = 0; j < 4; j++) {
                MMA(acc[im][2*j],   ah[im], bh[j][0], bh[j][1]);
                MMA(acc[im][2*j+1], ah[im], bh[j][2], bh[j][3]);
                MMA(acc[im][2*j],   al[im], bh[j][0], bh[j][1]);
                MMA(acc[im][2*j+1], al[im], bh[j][2], bh[j][3]);
                MMA(acc[im][2*j],   ah[im], bl[j][0], bl[j][1]);
                MMA(acc[im][2*j+1], ah[im], bl[j][2], bl[j][3]);
            }
        }
    }
}

__global__ void __launch_bounds__(256, 1) gemm_kernel(
    const float* __restrict__ b_proj, const float* __restrict__ b_sigma,
    const float* __restrict__ b_psi, float* __restrict__ out_rfeat)
{
    extern __shared__ char smem[];
    uint32_t sb = smem_u32(smem);
    int tid = threadIdx.x;
    int wid = tid >> 5, lane = tid & 31;
    int nt = blockIdx.x & 15;       // N-tile fastest: A reuse in L2
    int mt = blockIdx.x >> 4;
    int m0 = mt * MTILE, n0 = nt * NTILE;
    int wm = (wid >> 1) * 32, wn = (wid & 1) * 64;

    float acc[2][8][4];
#pragma unroll
    for (int a = 0; a < 2; a++)
#pragma unroll
        for (int b = 0; b < 8; b++)
#pragma unroll
            for (int c = 0; c < 4; c++) acc[a][b][c] = 0.f;

    load_chunk(sb + 0 * STAGE_BYTES, 0, m0, n0, tid);
    load_chunk(sb + 1 * STAGE_BYTES, 1, m0, n0, tid);

    for (int c = 0; c < NCH; c++) {
        asm volatile("cp.async.wait_group 1;" ::: "memory");
        __syncthreads();
        if (c + 2 < NCH) {
            int s = (c + 2) % STAGES;
            load_chunk(sb + s * STAGE_BYTES, c + 2, m0, n0, tid);
        }
        compute_chunk(sb + (c % STAGES) * STAGE_BYTES, acc, wm, wn, lane);
        __syncthreads();
    }

    // Epilogue: fused bias, route by N-tile to dest matrix
    int mat = nt >> 2;
    const float* bias = (mat == 0) ? b_proj : (mat == 1) ? b_sigma
                      : (mat == 2) ? b_psi : nullptr;
    float* dest = (mat == 0) ? out_rfeat : (mat == 1) ? g_sig
                : (mat == 2) ? g_psi : g_v;
    int colbase = (nt & 3) * 128;
    int groupID = lane >> 2, tig = lane & 3;

#pragma unroll
    for (int im = 0; im < 2; im++) {
#pragma unroll
        for (int in = 0; in < 8; in++) {
            int col = colbase + wn + in * 8 + tig * 2;
            float2 bv = make_float2(0.f, 0.f);
            if (bias) bv = __ldg((const float2*)&bias[col]);
            int row0 = m0 + wm + im * 16 + groupID;
            float2 v0, v1;
            v0.x = acc[im][in][0] + bv.x; v0.y = acc[im][in][1] + bv.y;
            v1.x = acc[im][in][2] + bv.x; v1.y = acc[im][in][3] + bv.y;
            *(float2*)&dest[(size_t)row0 * PDIM + col]       = v0;
            *(float2*)&dest[(size_t)(row0 + 8) * PDIM + col] = v1;
        }
    }
}

// ---------------------------------------------------------------------------
// Attention: per-head softmax(sig psi^T) @ v   (1 CTA per head, 256 threads)
// ---------------------------------------------------------------------------
__global__ void __launch_bounds__(256, 1) attn_kernel(float* __restrict__ out_rhat) {
    extern __shared__ float as[];
    float* psi_s = as;                        // 36*512
    float* v_s   = as + NOBJ * PDIM;          // 36*512
    float* l_s   = as + 2 * NOBJ * PDIM;      // 36*36
    int h = blockIdx.x;
    int tid = threadIdx.x;
    size_t base = (size_t)h * NOBJ;

    const float4* gp = (const float4*)(g_psi + base * PDIM);
    const float4* gv = (const float4*)(g_v   + base * PDIM);
    float4* sp = (float4*)psi_s;
    float4* sv = (float4*)v_s;
#pragma unroll
    for (int q = 0; q < 18; q++) {            // 4608 float4s
        int i = tid + q * 256;
        sp[i] = gp[i];
        sv[i] = gv[i];
    }
    __syncthreads();

    // logits: l[n][m] = dot(sig[n], psi[m]) over 512
    if (tid < 216) {
        int n = tid % 36, g = tid / 36;       // lanes mostly share g -> psi broadcast
        float a0 = 0, a1 = 0, a2 = 0, a3 = 0, a4 = 0, a5 = 0;
        const float4* sg = (const float4*)(g_sig + (base + n) * PDIM);
        const float4* p0 = (const float4*)&psi_s[(g * 6 + 0) * PDIM];
        const float4* p1 = (const float4*)&psi_s[(g * 6 + 1) * PDIM];
        const float4* p2 = (const float4*)&psi_s[(g * 6 + 2) * PDIM];
        const float4* p3 = (const float4*)&psi_s[(g * 6 + 3) * PDIM];
        const float4* p4 = (const float4*)&psi_s[(g * 6 + 4) * PDIM];
        const float4* p5 = (const float4*)&psi_s[(g * 6 + 5) * PDIM];
        for (int k = 0; k < 128; k++) {
            float4 s = __ldg(&sg[k]);
            float4 p;
            p = p0[k]; a0 += s.x * p.x + s.y * p.y + s.z * p.z + s.w * p.w;
            p = p1[k]; a1 += s.x * p.x + s.y * p.y + s.z * p.z + s.w * p.w;
            p = p2[k]; a2 += s.x * p.x + s.y * p.y + s.z * p.z + s.w * p.w;
            p = p3[k]; a3 += s.x * p.x + s.y * p.y + s.z * p.z + s.w * p.w;
            p = p4[k]; a4 += s.x * p.x + s.y * p.y + s.z * p.z + s.w * p.w;
            p = p5[k]; a5 += s.x * p.x + s.y * p.y + s.z * p.z + s.w * p.w;
        }
        l_s[n * 36 + g * 6 + 0] = a0;
        l_s[n * 36 + g * 6 + 1] = a1;
        l_s[n * 36 + g * 6 + 2] = a2;
        l_s[n * 36 + g * 6 + 3] = a3;
        l_s[n * 36 + g * 6 + 4] = a4;
        l_s[n * 36 + g * 6 + 5] = a5;
    }
    __syncthreads();

    // row softmax
    if (tid < 36) {
        float row[36];
        float m = -1e30f;
#pragma unroll
        for (int j = 0; j < 36; j++) { row[j] = l_s[tid * 36 + j]; m = fmaxf(m, row[j]); }
        float ssum = 0.f;
#pragma unroll
        for (int j = 0; j < 36; j++) { float e = __expf(row[j] - m); row[j] = e; ssum += e; }
        float inv = 1.f / ssum;
#pragma unroll
        for (int j = 0; j < 36; j++) l_s[tid * 36 + j] = row[j] * inv;
    }
    __syncthreads();

    // AV: out[n][p] = sum_m a[n][m] v[m][p]
    float4* vo = (float4*)(out_rhat + base * PDIM);
#pragma unroll
    for (int q = 0; q < 18; q++) {
        int o = tid + q * 256;                 // 0..4607
        int n = o >> 7, c4 = o & 127;
        float4 acc = make_float4(0.f, 0.f, 0.f, 0.f);
        const float* arow = &l_s[n * 36];
        const float4* vcol = (const float4*)v_s + c4;
#pragma unroll 4
        for (int m = 0; m < 36; m++) {
            float a = arow[m];
            float4 vv = vcol[m * 128];
            acc.x += a * vv.x; acc.y += a * vv.y; acc.z += a * vv.z; acc.w += a * vv.w;
        }
        vo[o] = acc;
    }
}

// ---------------------------------------------------------------------------
// Launcher
// ---------------------------------------------------------------------------
extern "C" void kernel_launch(void* const* d_in, const int* in_sizes, int n_in,
                              void* d_out, int out_size) {
    const float* x       = (const float*)d_in[0];
    const float* W_proj  = (const float*)d_in[1];
    const float* b_proj  = (const float*)d_in[2];
    const float* W_sigma = (const float*)d_in[3];
    const float* b_sigma = (const float*)d_in[4];
    const float* W_psi   = (const float*)d_in[5];
    const float* b_psi   = (const float*)d_in[6];
    const float* W_r     = (const float*)d_in[7];
    float* out = (float*)d_out;

    cudaFuncSetAttribute(gemm_kernel, cudaFuncAttributeMaxDynamicSharedMemorySize, GEMM_SMEM);
    cudaFuncSetAttribute(attn_kernel, cudaFuncAttributeMaxDynamicSharedMemorySize, ATTN_SMEM);

    long n4 = (long)MROWS * DIN / 4;
    split_x_kernel<<<8192, 256>>>(x, n4);
    split_w_kernel<<<(NCAT * DIN + 255) / 256, 256>>>(W_proj, W_sigma, W_psi, W_r);
    gemm_kernel<<<(MROWS / MTILE) * (NCAT / NTILE), 256, GEMM_SMEM>>>(
        b_proj, b_sigma, b_psi, out);
    attn_kernel<<<HEADS, 256, ATTN_SMEM>>>(out + OUT_HALF);
}

// round 5
// speedup vs baseline: 1.0196x; 1.0196x over previous
#include <cuda_runtime.h>
#include <cuda_bf16.h>
#include <cstdint>

// ---------------------------------------------------------------------------
// Problem constants
// ---------------------------------------------------------------------------
#define BATCH   32
#define FRAMES  32
#define NOBJ    36
#define DIN     2048
#define PDIM    512
#define MROWS   (BATCH*FRAMES*NOBJ)     // 36864
#define HEADS   (BATCH*FRAMES)          // 1024
#define NCAT    (4*PDIM)                // 2048 concat output cols
#define NCH     (DIN/64)                // 32 K-chunks of 64

// GEMM tiling: 128x256 CTA tile, 512 threads (16 warps, 4x4), 2 smem stages
#define MTILE   128
#define NTILE   256

// smem stage layout (bytes): AH 16K | AL 16K | BH 32K | BL 32K  = 96K/stage
#define OFF_AH  0
#define OFF_AL  16384
#define OFF_BH  32768
#define OFF_BL  65536
#define STAGE_BYTES 98304
#define GEMM_SMEM  (2*STAGE_BYTES)      // 196608

// attention smem: v (36*512 f32) + logits (36*36) + transposed probs (36*40)
#define ATTN_SMEM  ((NOBJ*PDIM + NOBJ*NOBJ + NOBJ*40)*4)   // 84672 bytes

#define OUT_HALF   ((size_t)MROWS*PDIM)

// ---------------------------------------------------------------------------
// Device scratch (static __device__ globals; runtime allocation is forbidden)
// ---------------------------------------------------------------------------
__device__ __nv_bfloat16 g_xh[(size_t)MROWS*DIN];
__device__ __nv_bfloat16 g_xl[(size_t)MROWS*DIN];
__device__ __nv_bfloat16 g_wth[(size_t)NCAT*DIN];   // [n][k], K-major
__device__ __nv_bfloat16 g_wtl[(size_t)NCAT*DIN];
__device__ float g_sig[(size_t)MROWS*PDIM];
__device__ float g_psi[(size_t)MROWS*PDIM];
__device__ float g_v  [(size_t)MROWS*PDIM];

// ---------------------------------------------------------------------------
// PTX helpers (baseline-PTX features only: cp.async, ldmatrix, mma.sync)
// ---------------------------------------------------------------------------
__device__ __forceinline__ uint32_t smem_u32(const void* p) {
    uint32_t a;
    asm("{ .reg .u64 t; cvta.to.shared.u64 t, %1; cvt.u32.u64 %0, t; }"
        : "=r"(a) : "l"(p));
    return a;
}

__device__ __forceinline__ void cp16(uint32_t s, const void* g) {
    asm volatile("cp.async.cg.shared.global [%0], [%1], 16;\n" :: "r"(s), "l"(g) : "memory");
}

#define LDSM4(R, A) \
    asm volatile("ldmatrix.sync.aligned.m8n8.x4.shared.b16 {%0,%1,%2,%3}, [%4];" \
        : "=r"((R)[0]), "=r"((R)[1]), "=r"((R)[2]), "=r"((R)[3]) : "r"(A))

#define MMA(C, A, B0, B1) \
    asm volatile("mma.sync.aligned.m16n8k16.row.col.f32.bf16.bf16.f32 " \
        "{%0,%1,%2,%3}, {%4,%5,%6,%7}, {%8,%9}, {%0,%1,%2,%3};" \
        : "+f"((C)[0]), "+f"((C)[1]), "+f"((C)[2]), "+f"((C)[3]) \
        : "r"((A)[0]), "r"((A)[1]), "r"((A)[2]), "r"((A)[3]), "r"(B0), "r"(B1))

// ---------------------------------------------------------------------------
// Prep kernels: fp32 -> (bf16 hi, bf16 lo) splits
// ---------------------------------------------------------------------------
__global__ void split_x_kernel(const float* __restrict__ x, long n4) {
    long i = blockIdx.x * (long)blockDim.x + threadIdx.x;
    long stride = (long)gridDim.x * blockDim.x;
    __nv_bfloat162* xh2 = reinterpret_cast<__nv_bfloat162*>(g_xh);
    __nv_bfloat162* xl2 = reinterpret_cast<__nv_bfloat162*>(g_xl);
    for (; i < n4; i += stride) {
        float4 v = reinterpret_cast<const float4*>(x)[i];
        __nv_bfloat16 h0 = __float2bfloat16(v.x);
        __nv_bfloat16 h1 = __float2bfloat16(v.y);
        __nv_bfloat16 h2 = __float2bfloat16(v.z);
        __nv_bfloat16 h3 = __float2bfloat16(v.w);
        __nv_bfloat16 l0 = __float2bfloat16(v.x - __bfloat162float(h0));
        __nv_bfloat16 l1 = __float2bfloat16(v.y - __bfloat162float(h1));
        __nv_bfloat16 l2 = __float2bfloat16(v.z - __bfloat162float(h2));
        __nv_bfloat16 l3 = __float2bfloat16(v.w - __bfloat162float(h3));
        __nv_bfloat162 hA; hA.x = h0; hA.y = h1;
        __nv_bfloat162 hB; hB.x = h2; hB.y = h3;
        __nv_bfloat162 lA; lA.x = l0; lA.y = l1;
        __nv_bfloat162 lB; lB.x = l2; lB.y = l3;
        xh2[2*i]   = hA; xh2[2*i+1] = hB;
        xl2[2*i]   = lA; xl2[2*i+1] = lB;
    }
}

__global__ void split_w_kernel(const float* __restrict__ Wp, const float* __restrict__ Ws,
                               const float* __restrict__ Wq, const float* __restrict__ Wr) {
    long t = blockIdx.x * (long)blockDim.x + threadIdx.x;   // over NCAT*DIN
    if (t >= (long)NCAT * DIN) return;
    int n = (int)(t >> 11);        // /DIN
    int k = (int)(t & (DIN - 1));
    int mat = n >> 9, p = n & 511;
    const float* W = (mat == 0) ? Wp : (mat == 1) ? Ws : (mat == 2) ? Wq : Wr;
    float w = W[(size_t)k * PDIM + p];
    __nv_bfloat16 h = __float2bfloat16(w);
    g_wth[t] = h;
    g_wtl[t] = __float2bfloat16(w - __bfloat162float(h));
}

// ---------------------------------------------------------------------------
// GEMM: out[m][n] = sum_k x[m][k] * Wcat[k][n], bf16 3-pass, fp32 accumulate
// mma.sync.m16n8k16 (HMMA); 512 threads, warp grid 4x4, warp tile 32x64
// ---------------------------------------------------------------------------
__device__ __forceinline__ void load_chunk(uint32_t sbase, int kc, int m0, int n0, int tid) {
    const char* xh = (const char*)g_xh;
    const char* xl = (const char*)g_xl;
    const char* bh = (const char*)g_wth;
    const char* bl = (const char*)g_wtl;
    size_t kcoff = (size_t)kc * 128;   // 64 bf16 = 128 bytes
#pragma unroll
    for (int q = 0; q < 2; q++) {                 // A: 128 rows x 8 x 16B
        int j = tid + q * 512;
        int r = j >> 3, i = j & 7;
        uint32_t so = (uint32_t)(r * 128 + ((i * 16) ^ ((r & 7) << 4)));
        size_t goA = ((size_t)(m0 + r)) * (DIN * 2) + kcoff + i * 16;
        cp16(sbase + OFF_AH + so, xh + goA);
        cp16(sbase + OFF_AL + so, xl + goA);
    }
#pragma unroll
    for (int q = 0; q < 4; q++) {                 // B: 256 rows x 8 x 16B
        int j = tid + q * 512;
        int r = j >> 3, i = j & 7;
        uint32_t so = (uint32_t)(r * 128 + ((i * 16) ^ ((r & 7) << 4)));
        size_t goB = ((size_t)(n0 + r)) * (DIN * 2) + kcoff + i * 16;
        cp16(sbase + OFF_BH + so, bh + goB);
        cp16(sbase + OFF_BL + so, bl + goB);
    }
    asm volatile("cp.async.commit_group;\n" ::: "memory");
}

__device__ __forceinline__ void compute_chunk(uint32_t sbase, float (*acc)[8][4],
                                              int wm, int wn, int lane) {
    int r_off  = lane & 15;
    int kseg   = (lane >> 4) << 3;            // A: k half select
    int n_off  = (lane & 7) + ((lane >> 4) << 3);
    int ksegb  = ((lane >> 3) & 1) << 3;      // B: k half select
#pragma unroll
    for (int kk = 0; kk < 4; kk++) {          // 4 x k16 per 64-chunk
        uint32_t ah[2][4], al[2][4], b[4][4];
#pragma unroll
        for (int im = 0; im < 2; im++) {
            uint32_t row = wm + im * 16 + r_off;
            uint32_t kb  = (uint32_t)((kk * 16 + kseg) * 2);
            uint32_t off = row * 128 + (kb ^ ((row & 7) << 4));
            LDSM4(ah[im], sbase + OFF_AH + off);
            LDSM4(al[im], sbase + OFF_AL + off);
        }
        // B-hi fragments
#pragma unroll
        for (int j = 0; j < 4; j++) {
            uint32_t row = wn + j * 16 + n_off;
            uint32_t kb  = (uint32_t)((kk * 16 + ksegb) * 2);
            uint32_t off = row * 128 + (kb ^ ((row & 7) << 4));
            LDSM4(b[j], sbase + OFF_BH + off);
        }
        // pass 1: Ah * Bh  (16 independent accumulator chains)
#pragma unroll
        for (int im = 0; im < 2; im++)
#pragma unroll
            for (int j = 0; j < 4; j++) {
                MMA(acc[im][2*j],   ah[im], b[j][0], b[j][1]);
                MMA(acc[im][2*j+1], ah[im], b[j][2], b[j][3]);
            }
        // pass 2: Al * Bh
#pragma unroll
        for (int im = 0; im < 2; im++)
#pragma unroll
            for (int j = 0; j < 4; j++) {
                MMA(acc[im][2*j],   al[im], b[j][0], b[j][1]);
                MMA(acc[im][2*j+1], al[im], b[j][2], b[j][3]);
            }
        // B-lo fragments (recycle registers)
#pragma unroll
        for (int j = 0; j < 4; j++) {
            uint32_t row = wn + j * 16 + n_off;
            uint32_t kb  = (uint32_t)((kk * 16 + ksegb) * 2);
            uint32_t off = row * 128 + (kb ^ ((row & 7) << 4));
            LDSM4(b[j], sbase + OFF_BL + off);
        }
        // pass 3: Ah * Bl
#pragma unroll
        for (int im = 0; im < 2; im++)
#pragma unroll
            for (int j = 0; j < 4; j++) {
                MMA(acc[im][2*j],   ah[im], b[j][0], b[j][1]);
                MMA(acc[im][2*j+1], ah[im], b[j][2], b[j][3]);
            }
    }
}

__global__ void __launch_bounds__(512, 1) gemm_kernel(
    const float* __restrict__ b_proj, const float* __restrict__ b_sigma,
    const float* __restrict__ b_psi, float* __restrict__ out_rfeat)
{
    extern __shared__ char smem[];
    uint32_t sb = smem_u32(smem);
    int tid = threadIdx.x;
    int wid = tid >> 5, lane = tid & 31;
    int nt = blockIdx.x & 7;        // N-tile fastest: A reuse in L2
    int mt = blockIdx.x >> 3;
    int m0 = mt * MTILE, n0 = nt * NTILE;
    int wm = (wid >> 2) * 32, wn = (wid & 3) * 64;

    float acc[2][8][4];
#pragma unroll
    for (int a = 0; a < 2; a++)
#pragma unroll
        for (int b = 0; b < 8; b++)
#pragma unroll
            for (int c = 0; c < 4; c++) acc[a][b][c] = 0.f;

    load_chunk(sb, 0, m0, n0, tid);

    for (int c = 0; c < NCH; c++) {
        if (c + 1 < NCH) {
            load_chunk(sb + ((c + 1) & 1) * STAGE_BYTES, c + 1, m0, n0, tid);
            asm volatile("cp.async.wait_group 1;" ::: "memory");
        } else {
            asm volatile("cp.async.wait_group 0;" ::: "memory");
        }
        __syncthreads();
        compute_chunk(sb + (c & 1) * STAGE_BYTES, acc, wm, wn, lane);
        __syncthreads();
    }

    // Epilogue: fused bias, route by N-tile to dest matrix
    int mat = nt >> 1;
    const float* bias = (mat == 0) ? b_proj : (mat == 1) ? b_sigma
                      : (mat == 2) ? b_psi : nullptr;
    float* dest = (mat == 0) ? out_rfeat : (mat == 1) ? g_sig
                : (mat == 2) ? g_psi : g_v;
    int colbase = (nt & 1) * 256;
    int groupID = lane >> 2, tig = lane & 3;

#pragma unroll
    for (int im = 0; im < 2; im++) {
#pragma unroll
        for (int in = 0; in < 8; in++) {
            int col = colbase + wn + in * 8 + tig * 2;
            float2 bv = make_float2(0.f, 0.f);
            if (bias) bv = __ldg((const float2*)&bias[col]);
            int row0 = m0 + wm + im * 16 + groupID;
            float2 v0, v1;
            v0.x = acc[im][in][0] + bv.x; v0.y = acc[im][in][1] + bv.y;
            v1.x = acc[im][in][2] + bv.x; v1.y = acc[im][in][3] + bv.y;
            *(float2*)&dest[(size_t)row0 * PDIM + col]       = v0;
            *(float2*)&dest[(size_t)(row0 + 8) * PDIM + col] = v1;
        }
    }
}

// ---------------------------------------------------------------------------
// Attention: per-head softmax(sig psi^T) @ v   (1 CTA per head, 256 threads,
// 2 CTAs/SM; only v staged in smem, psi/sig streamed via broadcast loads)
// ---------------------------------------------------------------------------
__global__ void __launch_bounds__(256, 2) attn_kernel(float* __restrict__ out_rhat) {
    extern __shared__ float as[];
    float* v_s = as;                          // 36*512
    float* l_s = as + NOBJ * PDIM;            // 36*36   logits, n-major
    float* l_t = l_s + NOBJ * NOBJ;           // 36*40   probs, m-major (padded)
    int h = blockIdx.x;
    int tid = threadIdx.x;
    size_t base = (size_t)h * NOBJ;

    const float4* gv = (const float4*)(g_v + base * PDIM);
    float4* sv = (float4*)v_s;
#pragma unroll
    for (int q = 0; q < 18; q++) {            // 4608 float4s
        int i = tid + q * 256;
        sv[i] = gv[i];
    }
    __syncthreads();

    // logits: l[n][m] = dot(sig[n], psi[m]) over 512; psi via broadcast LDG
    if (tid < 216) {
        int n = tid % 36, g = tid / 36;       // warp lanes share g -> psi broadcast
        float a0 = 0, a1 = 0, a2 = 0, a3 = 0, a4 = 0, a5 = 0;
        const float4* sg = (const float4*)(g_sig + (base + n) * PDIM);
        const float4* p0 = (const float4*)(g_psi + (base + g * 6 + 0) * PDIM);
        const float4* p1 = (const float4*)(g_psi + (base + g * 6 + 1) * PDIM);
        const float4* p2 = (const float4*)(g_psi + (base + g * 6 + 2) * PDIM);
        const float4* p3 = (const float4*)(g_psi + (base + g * 6 + 3) * PDIM);
        const float4* p4 = (const float4*)(g_psi + (base + g * 6 + 4) * PDIM);
        const float4* p5 = (const float4*)(g_psi + (base + g * 6 + 5) * PDIM);
        for (int k = 0; k < 128; k++) {
            float4 s = __ldg(&sg[k]);
            float4 p;
            p = __ldg(&p0[k]); a0 += s.x * p.x + s.y * p.y + s.z * p.z + s.w * p.w;
            p = __ldg(&p1[k]); a1 += s.x * p.x + s.y * p.y + s.z * p.z + s.w * p.w;
            p = __ldg(&p2[k]); a2 += s.x * p.x + s.y * p.y + s.z * p.z + s.w * p.w;
            p = __ldg(&p3[k]); a3 += s.x * p.x + s.y * p.y + s.z * p.z + s.w * p.w;
            p = __ldg(&p4[k]); a4 += s.x * p.x + s.y * p.y + s.z * p.z + s.w * p.w;
            p = __ldg(&p5[k]); a5 += s.x * p.x + s.y * p.y + s.z * p.z + s.w * p.w;
        }
        l_s[n * 36 + g * 6 + 0] = a0;
        l_s[n * 36 + g * 6 + 1] = a1;
        l_s[n * 36 + g * 6 + 2] = a2;
        l_s[n * 36 + g * 6 + 3] = a3;
        l_s[n * 36 + g * 6 + 4] = a4;
        l_s[n * 36 + g * 6 + 5] = a5;
    }
    __syncthreads();

    // row softmax; write probs transposed (m-major) for vectorized AV loads
    if (tid < 36) {
        float row[36];
        float m = -1e30f;
#pragma unroll
        for (int j = 0; j < 36; j++) { row[j] = l_s[tid * 36 + j]; m = fmaxf(m, row[j]); }
        float ssum = 0.f;
#pragma unroll
        for (int j = 0; j < 36; j++) { float e = __expf(row[j] - m); row[j] = e; ssum += e; }
        float inv = 1.f / ssum;
#pragma unroll
        for (int j = 0; j < 36; j++) l_t[j * 40 + tid] = row[j] * inv;
    }
    __syncthreads();

    // AV: out[n][p] = sum_m a[n][m] v[m][p]; each thread: 1 col-chunk x 18 rows
    int c4 = tid & 127, nh = tid >> 7;        // nh selects n in [nh*18, nh*18+18)
    float4 acc[18];
#pragma unroll
    for (int j = 0; j < 18; j++) acc[j] = make_float4(0.f, 0.f, 0.f, 0.f);
    const float4* vrow = (const float4*)v_s + c4;
#pragma unroll 4
    for (int m = 0; m < 36; m++) {
        float4 vv = vrow[m * 128];
#pragma unroll
        for (int jj = 0; jj < 9; jj++) {
            float2 aa = *(const float2*)&l_t[m * 40 + nh * 18 + jj * 2];
            acc[2*jj].x   += aa.x * vv.x; acc[2*jj].y   += aa.x * vv.y;
            acc[2*jj].z   += aa.x * vv.z; acc[2*jj].w   += aa.x * vv.w;
            acc[2*jj+1].x += aa.y * vv.x; acc[2*jj+1].y += aa.y * vv.y;
            acc[2*jj+1].z += aa.y * vv.z; acc[2*jj+1].w += aa.y * vv.w;
        }
    }
    float4* vo = (float4*)(out_rhat + base * PDIM);
#pragma unroll
    for (int j = 0; j < 18; j++) {
        int n = nh * 18 + j;
        vo[n * 128 + c4] = acc[j];
    }
}

// ---------------------------------------------------------------------------
// Launcher
// ---------------------------------------------------------------------------
extern "C" void kernel_launch(void* const* d_in, const int* in_sizes, int n_in,
                              void* d_out, int out_size) {
    const float* x       = (const float*)d_in[0];
    const float* W_proj  = (const float*)d_in[1];
    const float* b_proj  = (const float*)d_in[2];
    const float* W_sigma = (const float*)d_in[3];
    const float* b_sigma = (const float*)d_in[4];
    const float* W_psi   = (const float*)d_in[5];
    const float* b_psi   = (const float*)d_in[6];
    const float* W_r     = (const float*)d_in[7];
    float* out = (float*)d_out;

    cudaFuncSetAttribute(gemm_kernel, cudaFuncAttributeMaxDynamicSharedMemorySize, GEMM_SMEM);
    cudaFuncSetAttribute(attn_kernel, cudaFuncAttributeMaxDynamicSharedMemorySize, ATTN_SMEM);

    long n4 = (long)MROWS * DIN / 4;
    split_x_kernel<<<8192, 256>>>(x, n4);
    split_w_kernel<<<(NCAT * DIN + 255) / 256, 256>>>(W_proj, W_sigma, W_psi, W_r);
    gemm_kernel<<<(MROWS / MTILE) * (NCAT / NTILE), 512, GEMM_SMEM>>>(
        b_proj, b_sigma, b_psi, out);
    attn_kernel<<<HEADS, 256, ATTN_SMEM>>>(out + OUT_HALF);
}

// round 6
// speedup vs baseline: 1.3807x; 1.3542x over previous
#include <cuda_runtime.h>
#include <cuda_bf16.h>
#include <cuda_fp16.h>
#include <cstdint>

// ---------------------------------------------------------------------------
// Problem constants
// ---------------------------------------------------------------------------
#define BATCH   32
#define FRAMES  32
#define NOBJ    36
#define DIN     2048
#define PDIM    512
#define MROWS   (BATCH*FRAMES*NOBJ)     // 36864
#define HEADS   (BATCH*FRAMES)          // 1024
#define NCAT    (4*PDIM)                // 2048 concat output cols
#define NCH     (DIN/64)                // 32 K-chunks of 64

// GEMM tiling: 128x256 CTA tile, 512 threads (16 warps, 4x4)
#define MTILE   128
#define NTILE   256

// gemm3 (bf16 3-pass) stage layout: AH 16K | AL 16K | BH 32K | BL 32K = 96K
#define OFF_AH  0
#define OFF_AL  16384
#define OFF_BH  32768
#define OFF_BL  65536
#define STAGE3_BYTES 98304
#define GEMM3_SMEM  (2*STAGE3_BYTES)    // 196608

// gemm1 (fp16 1-pass) stage layout: AF 16K | BF 32K = 48K, 4 stages
#define OFF_AF  0
#define OFF_BF  16384
#define STAGE1_BYTES 49152
#define GEMM1_SMEM  (4*STAGE1_BYTES)    // 196608

// attention smem: v (36*512 f32) + logits (36*36) + transposed probs (36*40)
#define ATTN_SMEM  ((NOBJ*PDIM + NOBJ*NOBJ + NOBJ*40)*4)   // 84672 bytes

#define OUT_HALF   ((size_t)MROWS*PDIM)

// ---------------------------------------------------------------------------
// Device scratch (static __device__ globals; runtime allocation is forbidden)
// ---------------------------------------------------------------------------
__device__ __nv_bfloat16 g_xh[(size_t)MROWS*DIN];
__device__ __nv_bfloat16 g_xl[(size_t)MROWS*DIN];
__device__ __half        g_xf[(size_t)MROWS*DIN];
__device__ __nv_bfloat16 g_wth[(size_t)NCAT*DIN];   // [n][k], K-major (sig/psi rows)
__device__ __nv_bfloat16 g_wtl[(size_t)NCAT*DIN];
__device__ __half        g_wf [(size_t)NCAT*DIN];   // [n][k], K-major (proj/r rows)
__device__ float g_sig[(size_t)MROWS*PDIM];
__device__ float g_psi[(size_t)MROWS*PDIM];
__device__ float g_v  [(size_t)MROWS*PDIM];

// ---------------------------------------------------------------------------
// PTX helpers (baseline-PTX features only: cp.async, ldmatrix, mma.sync)
// ---------------------------------------------------------------------------
__device__ __forceinline__ uint32_t smem_u32(const void* p) {
    uint32_t a;
    asm("{ .reg .u64 t; cvta.to.shared.u64 t, %1; cvt.u32.u64 %0, t; }"
        : "=r"(a) : "l"(p));
    return a;
}

__device__ __forceinline__ void cp16(uint32_t s, const void* g) {
    asm volatile("cp.async.cg.shared.global [%0], [%1], 16;\n" :: "r"(s), "l"(g) : "memory");
}

#define LDSM4(R, A) \
    asm volatile("ldmatrix.sync.aligned.m8n8.x4.shared.b16 {%0,%1,%2,%3}, [%4];" \
        : "=r"((R)[0]), "=r"((R)[1]), "=r"((R)[2]), "=r"((R)[3]) : "r"(A))

#define MMA_BF16(C, A, B0, B1) \
    asm volatile("mma.sync.aligned.m16n8k16.row.col.f32.bf16.bf16.f32 " \
        "{%0,%1,%2,%3}, {%4,%5,%6,%7}, {%8,%9}, {%0,%1,%2,%3};" \
        : "+f"((C)[0]), "+f"((C)[1]), "+f"((C)[2]), "+f"((C)[3]) \
        : "r"((A)[0]), "r"((A)[1]), "r"((A)[2]), "r"((A)[3]), "r"(B0), "r"(B1))

#define MMA_F16(C, A, B0, B1) \
    asm volatile("mma.sync.aligned.m16n8k16.row.col.f32.f16.f16.f32 " \
        "{%0,%1,%2,%3}, {%4,%5,%6,%7}, {%8,%9}, {%0,%1,%2,%3};" \
        : "+f"((C)[0]), "+f"((C)[1]), "+f"((C)[2]), "+f"((C)[3]) \
        : "r"((A)[0]), "r"((A)[1]), "r"((A)[2]), "r"((A)[3]), "r"(B0), "r"(B1))

// ---------------------------------------------------------------------------
// Prep kernels: fp32 -> bf16 hi/lo (sig/psi path) and fp16 (proj/v path)
// ---------------------------------------------------------------------------
__global__ void split_x_kernel(const float* __restrict__ x, long n4) {
    long i = blockIdx.x * (long)blockDim.x + threadIdx.x;
    long stride = (long)gridDim.x * blockDim.x;
    __nv_bfloat162* xh2 = reinterpret_cast<__nv_bfloat162*>(g_xh);
    __nv_bfloat162* xl2 = reinterpret_cast<__nv_bfloat162*>(g_xl);
    __half2*        xf2 = reinterpret_cast<__half2*>(g_xf);
    for (; i < n4; i += stride) {
        float4 v = reinterpret_cast<const float4*>(x)[i];
        __nv_bfloat16 h0 = __float2bfloat16(v.x);
        __nv_bfloat16 h1 = __float2bfloat16(v.y);
        __nv_bfloat16 h2 = __float2bfloat16(v.z);
        __nv_bfloat16 h3 = __float2bfloat16(v.w);
        __nv_bfloat16 l0 = __float2bfloat16(v.x - __bfloat162float(h0));
        __nv_bfloat16 l1 = __float2bfloat16(v.y - __bfloat162float(h1));
        __nv_bfloat16 l2 = __float2bfloat16(v.z - __bfloat162float(h2));
        __nv_bfloat16 l3 = __float2bfloat16(v.w - __bfloat162float(h3));
        __nv_bfloat162 hA; hA.x = h0; hA.y = h1;
        __nv_bfloat162 hB; hB.x = h2; hB.y = h3;
        __nv_bfloat162 lA; lA.x = l0; lA.y = l1;
        __nv_bfloat162 lB; lB.x = l2; lB.y = l3;
        xh2[2*i]   = hA; xh2[2*i+1] = hB;
        xl2[2*i]   = lA; xl2[2*i+1] = lB;
        xf2[2*i]   = __floats2half2_rn(v.x, v.y);
        xf2[2*i+1] = __floats2half2_rn(v.z, v.w);
    }
}

__global__ void split_w_kernel(const float* __restrict__ Wp, const float* __restrict__ Ws,
                               const float* __restrict__ Wq, const float* __restrict__ Wr) {
    long t = blockIdx.x * (long)blockDim.x + threadIdx.x;   // over NCAT*DIN
    if (t >= (long)NCAT * DIN) return;
    int n = (int)(t >> 11);        // /DIN
    int k = (int)(t & (DIN - 1));
    int mat = n >> 9, p = n & 511;
    const float* W = (mat == 0) ? Wp : (mat == 1) ? Ws : (mat == 2) ? Wq : Wr;
    float w = W[(size_t)k * PDIM + p];
    if (mat == 1 || mat == 2) {
        __nv_bfloat16 h = __float2bfloat16(w);
        g_wth[t] = h;
        g_wtl[t] = __float2bfloat16(w - __bfloat162float(h));
    } else {
        g_wf[t] = __float2half_rn(w);
    }
}

// ---------------------------------------------------------------------------
// gemm3: sig/psi columns, bf16 3-pass (Ah*Bh + Al*Bh + Ah*Bl), fp32 accum
// ---------------------------------------------------------------------------
__device__ __forceinline__ void load_chunk3(uint32_t sbase, int kc, int m0, int n0, int tid) {
    const char* xh = (const char*)g_xh;
    const char* xl = (const char*)g_xl;
    const char* bh = (const char*)g_wth;
    const char* bl = (const char*)g_wtl;
    size_t kcoff = (size_t)kc * 128;   // 64 bf16 = 128 bytes
#pragma unroll
    for (int q = 0; q < 2; q++) {                 // A: 128 rows x 8 x 16B
        int j = tid + q * 512;
        int r = j >> 3, i = j & 7;
        uint32_t so = (uint32_t)(r * 128 + ((i * 16) ^ ((r & 7) << 4)));
        size_t goA = ((size_t)(m0 + r)) * (DIN * 2) + kcoff + i * 16;
        cp16(sbase + OFF_AH + so, xh + goA);
        cp16(sbase + OFF_AL + so, xl + goA);
    }
#pragma unroll
    for (int q = 0; q < 4; q++) {                 // B: 256 rows x 8 x 16B
        int j = tid + q * 512;
        int r = j >> 3, i = j & 7;
        uint32_t so = (uint32_t)(r * 128 + ((i * 16) ^ ((r & 7) << 4)));
        size_t goB = ((size_t)(n0 + r)) * (DIN * 2) + kcoff + i * 16;
        cp16(sbase + OFF_BH + so, bh + goB);
        cp16(sbase + OFF_BL + so, bl + goB);
    }
    asm volatile("cp.async.commit_group;\n" ::: "memory");
}

__device__ __forceinline__ void compute_chunk3(uint32_t sbase, float (*acc)[8][4],
                                               int wm, int wn, int lane) {
    int r_off  = lane & 15;
    int kseg   = (lane >> 4) << 3;
    int n_off  = (lane & 7) + ((lane >> 4) << 3);
    int ksegb  = ((lane >> 3) & 1) << 3;
#pragma unroll
    for (int kk = 0; kk < 4; kk++) {
        uint32_t ah[2][4], al[2][4], b[4][4];
#pragma unroll
        for (int im = 0; im < 2; im++) {
            uint32_t row = wm + im * 16 + r_off;
            uint32_t kb  = (uint32_t)((kk * 16 + kseg) * 2);
            uint32_t off = row * 128 + (kb ^ ((row & 7) << 4));
            LDSM4(ah[im], sbase + OFF_AH + off);
            LDSM4(al[im], sbase + OFF_AL + off);
        }
#pragma unroll
        for (int j = 0; j < 4; j++) {
            uint32_t row = wn + j * 16 + n_off;
            uint32_t kb  = (uint32_t)((kk * 16 + ksegb) * 2);
            uint32_t off = row * 128 + (kb ^ ((row & 7) << 4));
            LDSM4(b[j], sbase + OFF_BH + off);
        }
#pragma unroll
        for (int im = 0; im < 2; im++)
#pragma unroll
            for (int j = 0; j < 4; j++) {
                MMA_BF16(acc[im][2*j],   ah[im], b[j][0], b[j][1]);
                MMA_BF16(acc[im][2*j+1], ah[im], b[j][2], b[j][3]);
            }
#pragma unroll
        for (int im = 0; im < 2; im++)
#pragma unroll
            for (int j = 0; j < 4; j++) {
                MMA_BF16(acc[im][2*j],   al[im], b[j][0], b[j][1]);
                MMA_BF16(acc[im][2*j+1], al[im], b[j][2], b[j][3]);
            }
#pragma unroll
        for (int j = 0; j < 4; j++) {
            uint32_t row = wn + j * 16 + n_off;
            uint32_t kb  = (uint32_t)((kk * 16 + ksegb) * 2);
            uint32_t off = row * 128 + (kb ^ ((row & 7) << 4));
            LDSM4(b[j], sbase + OFF_BL + off);
        }
#pragma unroll
        for (int im = 0; im < 2; im++)
#pragma unroll
            for (int j = 0; j < 4; j++) {
                MMA_BF16(acc[im][2*j],   ah[im], b[j][0], b[j][1]);
                MMA_BF16(acc[im][2*j+1], ah[im], b[j][2], b[j][3]);
            }
    }
}

__global__ void __launch_bounds__(512, 1) gemm3_kernel(
    const float* __restrict__ b_sigma, const float* __restrict__ b_psi)
{
    extern __shared__ char smem[];
    uint32_t sb = smem_u32(smem);
    int tid = threadIdx.x;
    int wid = tid >> 5, lane = tid & 31;
    int nt = blockIdx.x & 3;        // N-tile fastest: A reuse in L2
    int mt = blockIdx.x >> 2;
    int m0 = mt * MTILE, n0 = 512 + nt * NTILE;   // concat cols 512..1535
    int wm = (wid >> 2) * 32, wn = (wid & 3) * 64;

    float acc[2][8][4];
#pragma unroll
    for (int a = 0; a < 2; a++)
#pragma unroll
        for (int b = 0; b < 8; b++)
#pragma unroll
            for (int c = 0; c < 4; c++) acc[a][b][c] = 0.f;

    load_chunk3(sb, 0, m0, n0, tid);

    for (int c = 0; c < NCH; c++) {
        if (c + 1 < NCH) {
            load_chunk3(sb + ((c + 1) & 1) * STAGE3_BYTES, c + 1, m0, n0, tid);
            asm volatile("cp.async.wait_group 1;" ::: "memory");
        } else {
            asm volatile("cp.async.wait_group 0;" ::: "memory");
        }
        __syncthreads();
        compute_chunk3(sb + (c & 1) * STAGE3_BYTES, acc, wm, wn, lane);
        __syncthreads();
    }

    const float* bias = (nt < 2) ? b_sigma : b_psi;
    float* dest = (nt < 2) ? g_sig : g_psi;
    int colbase = (nt & 1) * 256;
    int groupID = lane >> 2, tig = lane & 3;

#pragma unroll
    for (int im = 0; im < 2; im++) {
#pragma unroll
        for (int in = 0; in < 8; in++) {
            int col = colbase + wn + in * 8 + tig * 2;
            float2 bv = __ldg((const float2*)&bias[col]);
            int row0 = m0 + wm + im * 16 + groupID;
            float2 v0, v1;
            v0.x = acc[im][in][0] + bv.x; v0.y = acc[im][in][1] + bv.y;
            v1.x = acc[im][in][2] + bv.x; v1.y = acc[im][in][3] + bv.y;
            *(float2*)&dest[(size_t)row0 * PDIM + col]       = v0;
            *(float2*)&dest[(size_t)(row0 + 8) * PDIM + col] = v1;
        }
    }
}

// ---------------------------------------------------------------------------
// gemm1: r_feat / v columns, fp16 single pass, 4-stage cp.async pipeline
// ---------------------------------------------------------------------------
__device__ __forceinline__ void load_chunk1(uint32_t sbase, int kc, int m0, int n0, int tid) {
    const char* xf = (const char*)g_xf;
    const char* bf = (const char*)g_wf;
    size_t kcoff = (size_t)kc * 128;
#pragma unroll
    for (int q = 0; q < 2; q++) {                 // A: 128 rows
        int j = tid + q * 512;
        int r = j >> 3, i = j & 7;
        uint32_t so = (uint32_t)(r * 128 + ((i * 16) ^ ((r & 7) << 4)));
        size_t goA = ((size_t)(m0 + r)) * (DIN * 2) + kcoff + i * 16;
        cp16(sbase + OFF_AF + so, xf + goA);
    }
#pragma unroll
    for (int q = 0; q < 4; q++) {                 // B: 256 rows
        int j = tid + q * 512;
        int r = j >> 3, i = j & 7;
        uint32_t so = (uint32_t)(r * 128 + ((i * 16) ^ ((r & 7) << 4)));
        size_t goB = ((size_t)(n0 + r)) * (DIN * 2) + kcoff + i * 16;
        cp16(sbase + OFF_BF + so, bf + goB);
    }
    asm volatile("cp.async.commit_group;\n" ::: "memory");
}

__device__ __forceinline__ void compute_chunk1(uint32_t sbase, float (*acc)[8][4],
                                               int wm, int wn, int lane) {
    int r_off  = lane & 15;
    int kseg   = (lane >> 4) << 3;
    int n_off  = (lane & 7) + ((lane >> 4) << 3);
    int ksegb  = ((lane >> 3) & 1) << 3;
#pragma unroll
    for (int kk = 0; kk < 4; kk++) {
        uint32_t af[2][4], b[4][4];
#pragma unroll
        for (int im = 0; im < 2; im++) {
            uint32_t row = wm + im * 16 + r_off;
            uint32_t kb  = (uint32_t)((kk * 16 + kseg) * 2);
            uint32_t off = row * 128 + (kb ^ ((row & 7) << 4));
            LDSM4(af[im], sbase + OFF_AF + off);
        }
#pragma unroll
        for (int j = 0; j < 4; j++) {
            uint32_t row = wn + j * 16 + n_off;
            uint32_t kb  = (uint32_t)((kk * 16 + ksegb) * 2);
            uint32_t off = row * 128 + (kb ^ ((row & 7) << 4));
            LDSM4(b[j], sbase + OFF_BF + off);
        }
#pragma unroll
        for (int im = 0; im < 2; im++)
#pragma unroll
            for (int j = 0; j < 4; j++) {
                MMA_F16(acc[im][2*j],   af[im], b[j][0], b[j][1]);
                MMA_F16(acc[im][2*j+1], af[im], b[j][2], b[j][3]);
            }
    }
}

__global__ void __launch_bounds__(512, 1) gemm1_kernel(
    const float* __restrict__ b_proj, float* __restrict__ out_rfeat)
{
    extern __shared__ char smem[];
    uint32_t sb = smem_u32(smem);
    int tid = threadIdx.x;
    int wid = tid >> 5, lane = tid & 31;
    int nt = blockIdx.x & 3;
    int mt = blockIdx.x >> 2;
    int m0 = mt * MTILE;
    int n0 = (nt < 2) ? nt * NTILE : 1536 + (nt - 2) * NTILE;
    int wm = (wid >> 2) * 32, wn = (wid & 3) * 64;

    float acc[2][8][4];
#pragma unroll
    for (int a = 0; a < 2; a++)
#pragma unroll
        for (int b = 0; b < 8; b++)
#pragma unroll
            for (int c = 0; c < 4; c++) acc[a][b][c] = 0.f;

    load_chunk1(sb + 0 * STAGE1_BYTES, 0, m0, n0, tid);
    load_chunk1(sb + 1 * STAGE1_BYTES, 1, m0, n0, tid);
    load_chunk1(sb + 2 * STAGE1_BYTES, 2, m0, n0, tid);

    for (int c = 0; c < NCH; c++) {
        if (c + 3 < NCH) {
            load_chunk1(sb + ((c + 3) & 3) * STAGE1_BYTES, c + 3, m0, n0, tid);
            asm volatile("cp.async.wait_group 3;" ::: "memory");
        } else {
            asm volatile("cp.async.wait_group 0;" ::: "memory");
        }
        __syncthreads();
        compute_chunk1(sb + (c & 3) * STAGE1_BYTES, acc, wm, wn, lane);
        __syncthreads();
    }

    const float* bias = (nt < 2) ? b_proj : nullptr;
    float* dest = (nt < 2) ? out_rfeat : g_v;
    int colbase = (nt & 1) * 256;
    int groupID = lane >> 2, tig = lane & 3;

#pragma unroll
    for (int im = 0; im < 2; im++) {
#pragma unroll
        for (int in = 0; in < 8; in++) {
            int col = colbase + wn + in * 8 + tig * 2;
            float2 bv = make_float2(0.f, 0.f);
            if (bias) bv = __ldg((const float2*)&bias[col]);
            int row0 = m0 + wm + im * 16 + groupID;
            float2 v0, v1;
            v0.x = acc[im][in][0] + bv.x; v0.y = acc[im][in][1] + bv.y;
            v1.x = acc[im][in][2] + bv.x; v1.y = acc[im][in][3] + bv.y;
            *(float2*)&dest[(size_t)row0 * PDIM + col]       = v0;
            *(float2*)&dest[(size_t)(row0 + 8) * PDIM + col] = v1;
        }
    }
}

// ---------------------------------------------------------------------------
// Attention: per-head softmax(sig psi^T) @ v   (1 CTA per head, 256 threads,
// 2 CTAs/SM; only v staged in smem, psi/sig streamed via broadcast loads)
// ---------------------------------------------------------------------------
__global__ void __launch_bounds__(256, 2) attn_kernel(float* __restrict__ out_rhat) {
    extern __shared__ float as[];
    float* v_s = as;                          // 36*512
    float* l_s = as + NOBJ * PDIM;            // 36*36   logits, n-major
    float* l_t = l_s + NOBJ * NOBJ;           // 36*40   probs, m-major (padded)
    int h = blockIdx.x;
    int tid = threadIdx.x;
    size_t base = (size_t)h * NOBJ;

    const float4* gv = (const float4*)(g_v + base * PDIM);
    float4* sv = (float4*)v_s;
#pragma unroll
    for (int q = 0; q < 18; q++) {            // 4608 float4s
        int i = tid + q * 256;
        sv[i] = gv[i];
    }
    __syncthreads();

    // logits: l[n][m] = dot(sig[n], psi[m]) over 512; psi via broadcast LDG
    if (tid < 216) {
        int n = tid % 36, g = tid / 36;
        float a0 = 0, a1 = 0, a2 = 0, a3 = 0, a4 = 0, a5 = 0;
        const float4* sg = (const float4*)(g_sig + (base + n) * PDIM);
        const float4* p0 = (const float4*)(g_psi + (base + g * 6 + 0) * PDIM);
        const float4* p1 = (const float4*)(g_psi + (base + g * 6 + 1) * PDIM);
        const float4* p2 = (const float4*)(g_psi + (base + g * 6 + 2) * PDIM);
        const float4* p3 = (const float4*)(g_psi + (base + g * 6 + 3) * PDIM);
        const float4* p4 = (const float4*)(g_psi + (base + g * 6 + 4) * PDIM);
        const float4* p5 = (const float4*)(g_psi + (base + g * 6 + 5) * PDIM);
        for (int k = 0; k < 128; k++) {
            float4 s = __ldg(&sg[k]);
            float4 p;
            p = __ldg(&p0[k]); a0 += s.x * p.x + s.y * p.y + s.z * p.z + s.w * p.w;
            p = __ldg(&p1[k]); a1 += s.x * p.x + s.y * p.y + s.z * p.z + s.w * p.w;
            p = __ldg(&p2[k]); a2 += s.x * p.x + s.y * p.y + s.z * p.z + s.w * p.w;
            p = __ldg(&p3[k]); a3 += s.x * p.x + s.y * p.y + s.z * p.z + s.w * p.w;
            p = __ldg(&p4[k]); a4 += s.x * p.x + s.y * p.y + s.z * p.z + s.w * p.w;
            p = __ldg(&p5[k]); a5 += s.x * p.x + s.y * p.y + s.z * p.z + s.w * p.w;
        }
        l_s[n * 36 + g * 6 + 0] = a0;
        l_s[n * 36 + g * 6 + 1] = a1;
        l_s[n * 36 + g * 6 + 2] = a2;
        l_s[n * 36 + g * 6 + 3] = a3;
        l_s[n * 36 + g * 6 + 4] = a4;
        l_s[n * 36 + g * 6 + 5] = a5;
    }
    __syncthreads();

    // row softmax; write probs transposed (m-major) for vectorized AV loads
    if (tid < 36) {
        float row[36];
        float m = -1e30f;
#pragma unroll
        for (int j = 0; j < 36; j++) { row[j] = l_s[tid * 36 + j]; m = fmaxf(m, row[j]); }
        float ssum = 0.f;
#pragma unroll
        for (int j = 0; j < 36; j++) { float e = __expf(row[j] - m); row[j] = e; ssum += e; }
        float inv = 1.f / ssum;
#pragma unroll
        for (int j = 0; j < 36; j++) l_t[j * 40 + tid] = row[j] * inv;
    }
    __syncthreads();

    // AV: out[n][p] = sum_m a[n][m] v[m][p]; each thread: 1 col-chunk x 18 rows
    int c4 = tid & 127, nh = tid >> 7;
    float4 acc[18];
#pragma unroll
    for (int j = 0; j < 18; j++) acc[j] = make_float4(0.f, 0.f, 0.f, 0.f);
    const float4* vrow = (const float4*)v_s + c4;
#pragma unroll 4
    for (int m = 0; m < 36; m++) {
        float4 vv = vrow[m * 128];
#pragma unroll
        for (int jj = 0; jj < 9; jj++) {
            float2 aa = *(const float2*)&l_t[m * 40 + nh * 18 + jj * 2];
            acc[2*jj].x   += aa.x * vv.x; acc[2*jj].y   += aa.x * vv.y;
            acc[2*jj].z   += aa.x * vv.z; acc[2*jj].w   += aa.x * vv.w;
            acc[2*jj+1].x += aa.y * vv.x; acc[2*jj+1].y += aa.y * vv.y;
            acc[2*jj+1].z += aa.y * vv.z; acc[2*jj+1].w += aa.y * vv.w;
        }
    }
    float4* vo = (float4*)(out_rhat + base * PDIM);
#pragma unroll
    for (int j = 0; j < 18; j++) {
        int n = nh * 18 + j;
        vo[n * 128 + c4] = acc[j];
    }
}

// ---------------------------------------------------------------------------
// Launcher
// ---------------------------------------------------------------------------
extern "C" void kernel_launch(void* const* d_in, const int* in_sizes, int n_in,
                              void* d_out, int out_size) {
    const float* x       = (const float*)d_in[0];
    const float* W_proj  = (const float*)d_in[1];
    const float* b_proj  = (const float*)d_in[2];
    const float* W_sigma = (const float*)d_in[3];
    const float* b_sigma = (const float*)d_in[4];
    const float* W_psi   = (const float*)d_in[5];
    const float* b_psi   = (const float*)d_in[6];
    const float* W_r     = (const float*)d_in[7];
    float* out = (float*)d_out;

    cudaFuncSetAttribute(gemm3_kernel, cudaFuncAttributeMaxDynamicSharedMemorySize, GEMM3_SMEM);
    cudaFuncSetAttribute(gemm1_kernel, cudaFuncAttributeMaxDynamicSharedMemorySize, GEMM1_SMEM);
    cudaFuncSetAttribute(attn_kernel, cudaFuncAttributeMaxDynamicSharedMemorySize, ATTN_SMEM);

    long n4 = (long)MROWS * DIN / 4;
    split_x_kernel<<<8192, 256>>>(x, n4);
    split_w_kernel<<<(NCAT * DIN + 255) / 256, 256>>>(W_proj, W_sigma, W_psi, W_r);
    gemm3_kernel<<<(MROWS / MTILE) * 4, 512, GEMM3_SMEM>>>(b_sigma, b_psi);
    gemm1_kernel<<<(MROWS / MTILE) * 4, 512, GEMM1_SMEM>>>(b_proj, out);
    attn_kernel<<<HEADS, 256, ATTN_SMEM>>>(out + OUT_HALF);
}